// round 1
// baseline (speedup 1.0000x reference)
#include <cuda_runtime.h>
#include <math.h>

#define NN   200000
#define NPL  12500
#define NLVL 16
#define DEG  8
#define HD   128
#define G3   384
#define EPL  (NPL*DEG)
#define BM   20
#define NT   384

// Scratch (static device allocations are allowed; no runtime alloc)
__device__ float g_x [(size_t)NN*HD];   // 102.4 MB
__device__ float g_h [(size_t)NN*HD];   // 102.4 MB
__device__ float g_gx[(size_t)NN*G3];   // 307.2 MB

__device__ __forceinline__ float sigmf(float v){ return 1.f/(1.f+expf(-v)); }

// ---------------- scatter x = zeros.at[index_map].add(features) ----------------
__global__ void k_zero_x(){
    size_t i = (size_t)blockIdx.x*blockDim.x + threadIdx.x;
    if (i < (size_t)NN*HD) g_x[i] = 0.f;
}

__global__ void k_scatter(const float* __restrict__ f, const int* __restrict__ imap){
    int i = blockIdx.x*blockDim.x + threadIdx.x;
    if (i < NN*HD){
        int node = i >> 7, c = i & 127;
        atomicAdd(&g_x[(size_t)__ldg(&imap[node])*HD + c], f[i]);
    }
}

// ---------------- gx = A[rows,128] @ W[128,384] + b ----------------
// 384 threads: thread t owns output column t for BM rows.
__global__ void __launch_bounds__(NT) k_gemm(const float* __restrict__ A,
                                             const float* __restrict__ W,
                                             const float* __restrict__ bias,
                                             float* __restrict__ C){
    __shared__ float sA[BM][HD];
    const int row0 = blockIdx.x * BM;
    const int t = threadIdx.x;

    for (int i = t; i < BM*HD; i += NT){
        int r = i >> 7, c = i & 127;
        sA[r][c] = A[(size_t)(row0+r)*HD + c];
    }
    __syncthreads();

    float acc[BM];
    #pragma unroll
    for (int r = 0; r < BM; r++) acc[r] = 0.f;

    const int j = t;
    #pragma unroll 2
    for (int k0 = 0; k0 < HD; k0 += 4){
        float w0 = __ldg(&W[(size_t)(k0+0)*G3 + j]);
        float w1 = __ldg(&W[(size_t)(k0+1)*G3 + j]);
        float w2 = __ldg(&W[(size_t)(k0+2)*G3 + j]);
        float w3 = __ldg(&W[(size_t)(k0+3)*G3 + j]);
        #pragma unroll
        for (int r = 0; r < BM; r++){
            float4 a = *reinterpret_cast<const float4*>(&sA[r][k0]);
            acc[r] = fmaf(a.x, w0, acc[r]);
            acc[r] = fmaf(a.y, w1, acc[r]);
            acc[r] = fmaf(a.z, w2, acc[r]);
            acc[r] = fmaf(a.w, w3, acc[r]);
        }
    }
    float bj = __ldg(&bias[j]);
    #pragma unroll
    for (int r = 0; r < BM; r++)
        C[(size_t)(row0+r)*G3 + j] = acc[r] + bj;
}

// ---------------- level 0: m = 0 -> h = (1-z)*tanh(g3) ----------------
__global__ void k_level0(){
    int i = blockIdx.x*blockDim.x + threadIdx.x;
    if (i < NPL*HD){
        int node = i >> 7, c = i & 127;
        const float* gx = g_gx + (size_t)node*G3;
        float z = sigmf(gx[HD + c]);
        float n = tanhf(gx[2*HD + c]);
        g_h[(size_t)node*HD + c] = (1.f - z)*n;
    }
}

// ---------------- fused level step: gather mean -> gh = m@Wh -> GRU ----------------
__global__ void __launch_bounds__(NT) k_level(int lvl,
                                              const int*   __restrict__ esrc,
                                              const float* __restrict__ Wh){
    __shared__ float sM [BM][HD];    // 10.24 KB
    __shared__ float sGH[BM][G3];    // 30.72 KB
    const int s    = lvl*NPL;
    const int row0 = blockIdx.x*BM;  // local node index within level
    const int t    = threadIdx.x;
    const int* eb  = esrc + (size_t)(lvl-1)*EPL;

    // m[r][c] = mean over 8 sources of h[src][c]  (deg == 8 by construction)
    for (int i = t; i < BM*HD; i += NT){
        int r = i >> 7, c = i & 127;
        const int* ep = eb + (row0 + r)*DEG;
        float sum = 0.f;
        #pragma unroll
        for (int k = 0; k < DEG; k++)
            sum += g_h[(size_t)__ldg(&ep[k])*HD + c];
        sM[r][c] = sum * 0.125f;
    }
    __syncthreads();

    // gh = m @ Wh   (thread t owns column t for BM rows)
    float acc[BM];
    #pragma unroll
    for (int r = 0; r < BM; r++) acc[r] = 0.f;
    const int j = t;
    #pragma unroll 2
    for (int k0 = 0; k0 < HD; k0 += 4){
        float w0 = __ldg(&Wh[(size_t)(k0+0)*G3 + j]);
        float w1 = __ldg(&Wh[(size_t)(k0+1)*G3 + j]);
        float w2 = __ldg(&Wh[(size_t)(k0+2)*G3 + j]);
        float w3 = __ldg(&Wh[(size_t)(k0+3)*G3 + j]);
        #pragma unroll
        for (int r = 0; r < BM; r++){
            float4 a = *reinterpret_cast<const float4*>(&sM[r][k0]);
            acc[r] = fmaf(a.x, w0, acc[r]);
            acc[r] = fmaf(a.y, w1, acc[r]);
            acc[r] = fmaf(a.z, w2, acc[r]);
            acc[r] = fmaf(a.w, w3, acc[r]);
        }
    }
    #pragma unroll
    for (int r = 0; r < BM; r++) sGH[r][j] = acc[r];
    __syncthreads();

    // GRU gates
    for (int i = t; i < BM*HD; i += NT){
        int r = i >> 7, c = i & 127;
        int node = s + row0 + r;
        const float* gx = g_gx + (size_t)node*G3;
        float rg = sigmf(gx[c]        + sGH[r][c]);
        float z  = sigmf(gx[c + HD]   + sGH[r][c + HD]);
        float m  = sM[r][c];
        float nn = tanhf(gx[c + 2*HD] + rg*sGH[r][c + 2*HD]);
        g_h[(size_t)node*HD + c] = (1.f - z)*nn + z*m;
    }
}

// ---------------- out = h[index_map] ----------------
__global__ void k_gather(const int* __restrict__ imap, float* __restrict__ out){
    int i = blockIdx.x*blockDim.x + threadIdx.x;
    if (i < NN*HD){
        int node = i >> 7, c = i & 127;
        out[i] = g_h[(size_t)__ldg(&imap[node])*HD + c];
    }
}

extern "C" void kernel_launch(void* const* d_in, const int* in_sizes, int n_in,
                              void* d_out, int out_size){
    const float* feats = (const float*)d_in[0];
    const float* wx    = (const float*)d_in[1];  // (256,1,384)
    const float* wh    = (const float*)d_in[2];  // (2,128,1,384)
    const float* bs    = (const float*)d_in[3];  // (2,1,384)
    const int*   esrc  = (const int*)  d_in[4];
    // d_in[5] edge_dst unused: dsts are contiguous by construction (repeat, DEG=8)
    const int*   imap  = (const int*)  d_in[6];
    float*       out   = (float*)d_out;

    void *px, *ph, *pgx;
    cudaGetSymbolAddress(&px,  g_x);
    cudaGetSymbolAddress(&ph,  g_h);
    cudaGetSymbolAddress(&pgx, g_gx);

    const int EW = NN*HD;  // 25.6M elementwise items
    k_zero_x <<<(EW + 255)/256, 256>>>();
    k_scatter<<<(EW + 255)/256, 256>>>(feats, imap);

    for (int layer = 0; layer < 2; layer++){
        const float* A   = (layer == 0) ? (const float*)px : (const float*)ph;
        const float* Wx  = wx + (size_t)layer*HD*G3;
        const float* b   = bs + (size_t)layer*G3;
        const float* Whl = wh + (size_t)layer*HD*G3;

        k_gemm  <<<NN/BM, NT>>>(A, Wx, b, (float*)pgx);
        k_level0<<<(NPL*HD + 255)/256, 256>>>();
        for (int lvl = 1; lvl < NLVL; lvl++)
            k_level<<<NPL/BM, NT>>>(lvl, esrc, Whl);
    }

    k_gather<<<(EW + 255)/256, 256>>>(imap, out);
}

// round 3
// speedup vs baseline: 2.2959x; 2.2959x over previous
#include <cuda_runtime.h>
#include <cuda_bf16.h>
#include <stdint.h>
#include <math.h>

#define NN   200000
#define NPL  12500
#define NLVL 16
#define DEG  8
#define HD   128
#define G3   384
#define EPL  (NPL*DEG)

#define TM    64
#define NTHR  512
#define NCTA  ((NPL + TM - 1) / TM)   // 196

// A tile row pitch: 128 bf16 + 8 pad = 136 elems = 272B (bank-shift 4 words/row)
#define APITCH 272
// S accumulator pitch in floats: 512 + 4 pad
#define SPITCH 516

// dynamic smem layout (bytes)
#define OFF_AXH  0
#define OFF_AXL  17408
#define OFF_AMH  34816
#define OFF_AML  52224
#define OFF_S    69632                 // 64*516*4 = 132096
#define OFF_EDGE 201728                // 512 int
#define OFF_BIAS 203776                // 384 float
#define SMEM_DYN 205312

__device__ float    g_x[(size_t)NN*HD];
__device__ float    g_h[(size_t)NN*HD];
__device__ uint32_t g_bfrag[196608];   // [layer][g][part][kt(8)][nb(48)][lane(32)][j(2)]

// ---------------- helpers ----------------
__device__ __forceinline__ uint32_t smem_u32(const void* p){
    uint32_t a;
    asm("{ .reg .u64 t; cvta.to.shared.u64 t, %1; cvt.u32.u64 %0, t; }" : "=r"(a) : "l"(p));
    return a;
}
__device__ __forceinline__ void ldsm4(uint32_t* a, uint32_t addr){
    asm volatile("ldmatrix.sync.aligned.m8n8.x4.shared.b16 {%0,%1,%2,%3}, [%4];"
        : "=r"(a[0]), "=r"(a[1]), "=r"(a[2]), "=r"(a[3]) : "r"(addr));
}
__device__ __forceinline__ void mma_bf16(float* d, const uint32_t* a, const uint32_t* b){
    asm volatile("mma.sync.aligned.m16n8k16.row.col.f32.bf16.bf16.f32 "
        "{%0,%1,%2,%3}, {%4,%5,%6,%7}, {%8,%9}, {%0,%1,%2,%3};"
        : "+f"(d[0]), "+f"(d[1]), "+f"(d[2]), "+f"(d[3])
        : "r"(a[0]), "r"(a[1]), "r"(a[2]), "r"(a[3]), "r"(b[0]), "r"(b[1]));
}
__device__ __forceinline__ float sigmf(float v){ return 1.f / (1.f + __expf(-v)); }

// split 8 f32 -> hi/lo bf16, store as uint4 at padded (r, k0)
__device__ __forceinline__ void pack8(char* hi, char* lo, int r, int k0, float4 a, float4 b){
    float v[8] = {a.x, a.y, a.z, a.w, b.x, b.y, b.z, b.w};
    unsigned short hs[8], ls[8];
#pragma unroll
    for (int j = 0; j < 8; j++){
        __nv_bfloat16 h = __float2bfloat16(v[j]);
        __nv_bfloat16 l = __float2bfloat16(v[j] - __bfloat162float(h));
        hs[j] = __bfloat16_as_ushort(h);
        ls[j] = __bfloat16_as_ushort(l);
    }
    uint4 H, L;
    H.x = (uint32_t)hs[0] | ((uint32_t)hs[1] << 16);
    H.y = (uint32_t)hs[2] | ((uint32_t)hs[3] << 16);
    H.z = (uint32_t)hs[4] | ((uint32_t)hs[5] << 16);
    H.w = (uint32_t)hs[6] | ((uint32_t)hs[7] << 16);
    L.x = (uint32_t)ls[0] | ((uint32_t)ls[1] << 16);
    L.y = (uint32_t)ls[2] | ((uint32_t)ls[3] << 16);
    L.z = (uint32_t)ls[4] | ((uint32_t)ls[5] << 16);
    L.w = (uint32_t)ls[6] | ((uint32_t)ls[7] << 16);
    uint32_t o = (uint32_t)r * APITCH + (uint32_t)k0 * 2;
    *(uint4*)(hi + o) = H;
    *(uint4*)(lo + o) = L;
}

// ---------------- prep: weights -> bf16 hi/lo HMMA fragment arrays ----------------
__global__ void k_prep(const float* __restrict__ wx, const float* __restrict__ wh){
    int id = blockIdx.x * blockDim.x + threadIdx.x;
    if (id >= 196608) return;
    int pidx = id / 24576;                 // [layer(2)][g(2)][part(2)]
    int layer = pidx >> 2, g = (pidx >> 1) & 1, part = pidx & 1;
    int w = id % 24576;
    int kt = w / 3072;
    int rem = w % 3072;
    int nb = rem / 64;
    int rem2 = rem % 64;
    int lane = rem2 >> 1, j = rem2 & 1;
    int k = kt * 16 + (lane & 3) * 2 + 8 * j;
    int n = nb * 8 + (lane >> 2);
    const float* W = (g ? wh : wx) + (size_t)layer * HD * G3;
    float v0 = W[(size_t)k * G3 + n];
    float v1 = W[(size_t)(k + 1) * G3 + n];
    unsigned short p0, p1;
    __nv_bfloat16 h0 = __float2bfloat16(v0), h1 = __float2bfloat16(v1);
    if (part == 0){ p0 = __bfloat16_as_ushort(h0); p1 = __bfloat16_as_ushort(h1); }
    else {
        p0 = __bfloat16_as_ushort(__float2bfloat16(v0 - __bfloat162float(h0)));
        p1 = __bfloat16_as_ushort(__float2bfloat16(v1 - __bfloat162float(h1)));
    }
    g_bfrag[id] = (uint32_t)p0 | ((uint32_t)p1 << 16);
}

// ---------------- x = zeros.at[index_map].add(features) ----------------
__global__ void k_zero_x(){
    size_t i = (size_t)blockIdx.x * blockDim.x + threadIdx.x;
    if (i < (size_t)NN * HD) g_x[i] = 0.f;
}
__global__ void k_scatter(const float* __restrict__ f, const int* __restrict__ imap){
    int i = blockIdx.x * blockDim.x + threadIdx.x;
    if (i < NN * HD){
        int node = i >> 7, c = i & 127;
        atomicAdd(&g_x[(size_t)__ldg(&imap[node]) * HD + c], f[i]);
    }
}

// ---------------- GEMM phase: C(64x384) via 3-pass bf16 HMMA into S ----------------
// warp owns cols [warp*24, warp*24+24) over all 64 rows.
// isCx=false: store at S[col] (Ch; its n-part lands at 256..383).
// isCx=true : col<256 -> (addRZ? += : =) S[col]; col>=256 -> = S[col+128].
__device__ __forceinline__ void gemm_phase(
    uint32_t aHi, uint32_t aLo,
    const uint32_t* __restrict__ bHi, const uint32_t* __restrict__ bLo,
    float* __restrict__ S, int warp, int lane, bool isCx, bool addRZ)
{
    const int n0 = warp * 24;
    float acc[4][3][4];
#pragma unroll
    for (int rb = 0; rb < 4; rb++)
#pragma unroll
        for (int nb = 0; nb < 3; nb++)
#pragma unroll
            for (int q = 0; q < 4; q++) acc[rb][nb][q] = 0.f;

    const uint32_t laneOff = (uint32_t)(lane & 15) * APITCH + (uint32_t)((lane >> 4) << 4);

#pragma unroll
    for (int kt = 0; kt < 8; kt++){
        uint32_t BH[3][2], BL[3][2];
#pragma unroll
        for (int nb = 0; nb < 3; nb++){
            size_t idx = (size_t)kt * 3072 + (size_t)(n0 / 8 + nb) * 64 + (size_t)lane * 2;
            uint2 h = *(const uint2*)(bHi + idx);
            uint2 l = *(const uint2*)(bLo + idx);
            BH[nb][0] = h.x; BH[nb][1] = h.y;
            BL[nb][0] = l.x; BL[nb][1] = l.y;
        }
#pragma unroll
        for (int rb = 0; rb < 4; rb++){
            uint32_t ah[4], al[4];
            uint32_t ao = laneOff + (uint32_t)rb * 16 * APITCH + (uint32_t)kt * 32;
            ldsm4(ah, aHi + ao);
            ldsm4(al, aLo + ao);
#pragma unroll
            for (int nb = 0; nb < 3; nb++){
                mma_bf16(acc[rb][nb], ah, BH[nb]);
                mma_bf16(acc[rb][nb], al, BH[nb]);
                mma_bf16(acc[rb][nb], ah, BL[nb]);
            }
        }
    }

#pragma unroll
    for (int rb = 0; rb < 4; rb++){
#pragma unroll
        for (int nb = 0; nb < 3; nb++){
            int row = rb * 16 + (lane >> 2);
            int col = n0 + nb * 8 + (lane & 3) * 2;
            int scol = (isCx && col >= 256) ? col + 128 : col;
            float* p  = S + (size_t)row * SPITCH + scol;
            float* p2 = p + 8 * SPITCH;
            if (isCx && addRZ && col < 256){
                p [0] += acc[rb][nb][0]; p [1] += acc[rb][nb][1];
                p2[0] += acc[rb][nb][2]; p2[1] += acc[rb][nb][3];
            } else {
                p [0] = acc[rb][nb][0]; p [1] = acc[rb][nb][1];
                p2[0] = acc[rb][nb][2]; p2[1] = acc[rb][nb][3];
            }
        }
    }
}

// ---------------- fused level kernel ----------------
__global__ void __launch_bounds__(NTHR) k_fused(
    const float* __restrict__ xsrc,
    float* __restrict__ hdst,
    const int* __restrict__ esrc,
    const float* __restrict__ bias,
    int layer, int lvl)
{
    extern __shared__ char sm[];
    const uint32_t smb = smem_u32(sm);
    const int tid = threadIdx.x, warp = tid >> 5, lane = tid & 31;
    const int row0 = blockIdx.x * TM;
    const int s = lvl * NPL;

    int*   se = (int*)  (sm + OFF_EDGE);
    float* sb = (float*)(sm + OFF_BIAS);
    float* S  = (float*)(sm + OFF_S);

    if (lvl > 0 && tid < TM * DEG){
        int r = tid >> 3;
        int rr = (row0 + r < NPL) ? (row0 + r) : (NPL - 1);
        se[tid] = __ldg(&esrc[(size_t)(lvl - 1) * EPL + rr * DEG + (tid & 7)]);
    }
    if (tid < G3) sb[tid] = __ldg(&bias[tid]);
    __syncthreads();

    // build x A-tile
    for (int i = tid; i < TM * 16; i += NTHR){
        int r = i >> 4, k0 = (i & 15) * 8;
        int node = s + ((row0 + r < NPL) ? (row0 + r) : (NPL - 1));
        const float4* p = (const float4*)(xsrc + (size_t)node * HD + k0);
        pack8(sm + OFF_AXH, sm + OFF_AXL, r, k0, p[0], p[1]);
    }
    // build m A-tile (mean of 8 gathered h rows)
    if (lvl > 0){
        for (int i = tid; i < TM * 16; i += NTHR){
            int r = i >> 4, k0 = (i & 15) * 8;
            float4 s0 = make_float4(0.f, 0.f, 0.f, 0.f);
            float4 s1 = make_float4(0.f, 0.f, 0.f, 0.f);
#pragma unroll
            for (int e = 0; e < DEG; e++){
                int src = se[r * DEG + e];
                const float4* p = (const float4*)(hdst + (size_t)src * HD + k0);
                float4 v0 = p[0], v1 = p[1];
                s0.x += v0.x; s0.y += v0.y; s0.z += v0.z; s0.w += v0.w;
                s1.x += v1.x; s1.y += v1.y; s1.z += v1.z; s1.w += v1.w;
            }
            s0.x *= 0.125f; s0.y *= 0.125f; s0.z *= 0.125f; s0.w *= 0.125f;
            s1.x *= 0.125f; s1.y *= 0.125f; s1.z *= 0.125f; s1.w *= 0.125f;
            pack8(sm + OFF_AMH, sm + OFF_AML, r, k0, s0, s1);
        }
    }
    __syncthreads();

    const uint32_t* bWx_hi = g_bfrag + (size_t)((layer * 2 + 0) * 2 + 0) * 24576;
    const uint32_t* bWx_lo = g_bfrag + (size_t)((layer * 2 + 0) * 2 + 1) * 24576;
    const uint32_t* bWh_hi = g_bfrag + (size_t)((layer * 2 + 1) * 2 + 0) * 24576;
    const uint32_t* bWh_lo = g_bfrag + (size_t)((layer * 2 + 1) * 2 + 1) * 24576;

    if (lvl > 0){
        gemm_phase(smb + OFF_AMH, smb + OFF_AML, bWh_hi, bWh_lo, S, warp, lane, false, false);
        __syncthreads();
    }
    gemm_phase(smb + OFF_AXH, smb + OFF_AXL, bWx_hi, bWx_lo, S, warp, lane, true, lvl > 0);
    __syncthreads();

    // epilogue: thread -> row r = tid>>3, cols (tid&7)*16 .. +15
    {
        const int r = tid >> 3;
        const int nodeLocal = row0 + r;
        const bool ok = nodeLocal < NPL;
        const int gnode = s + nodeLocal;
        const float* Sr = S + (size_t)r * SPITCH;
#pragma unroll
        for (int half = 0; half < 2; half++){
            const int c0 = (tid & 7) * 16 + half * 8;
            float4 rA = *(const float4*)(Sr + c0);
            float4 rB = *(const float4*)(Sr + c0 + 4);
            float4 zA = *(const float4*)(Sr + 128 + c0);
            float4 zB = *(const float4*)(Sr + 128 + c0 + 4);
            float4 xA = *(const float4*)(Sr + 384 + c0);
            float4 xB = *(const float4*)(Sr + 384 + c0 + 4);
            float rv[8] = {rA.x, rA.y, rA.z, rA.w, rB.x, rB.y, rB.z, rB.w};
            float zv[8] = {zA.x, zA.y, zA.z, zA.w, zB.x, zB.y, zB.z, zB.w};
            float nx[8] = {xA.x, xA.y, xA.z, xA.w, xB.x, xB.y, xB.z, xB.w};
            float nh[8], mv[8];
            if (lvl > 0){
                float4 hA = *(const float4*)(Sr + 256 + c0);
                float4 hB = *(const float4*)(Sr + 256 + c0 + 4);
                nh[0]=hA.x; nh[1]=hA.y; nh[2]=hA.z; nh[3]=hA.w;
                nh[4]=hB.x; nh[5]=hB.y; nh[6]=hB.z; nh[7]=hB.w;
                uint32_t o = (uint32_t)r * APITCH + (uint32_t)c0 * 2;
                uint4 H = *(const uint4*)(sm + OFF_AMH + o);
                uint4 L = *(const uint4*)(sm + OFF_AML + o);
                const uint32_t hp[4] = {H.x, H.y, H.z, H.w};
                const uint32_t lp[4] = {L.x, L.y, L.z, L.w};
#pragma unroll
                for (int q = 0; q < 4; q++){
                    mv[q*2]   = __bfloat162float(__ushort_as_bfloat16((unsigned short)(hp[q] & 0xFFFF)))
                              + __bfloat162float(__ushort_as_bfloat16((unsigned short)(lp[q] & 0xFFFF)));
                    mv[q*2+1] = __bfloat162float(__ushort_as_bfloat16((unsigned short)(hp[q] >> 16)))
                              + __bfloat162float(__ushort_as_bfloat16((unsigned short)(lp[q] >> 16)));
                }
            } else {
#pragma unroll
                for (int q = 0; q < 8; q++){ nh[q] = 0.f; mv[q] = 0.f; }
            }
            float out[8];
#pragma unroll
            for (int q = 0; q < 8; q++){
                int c = c0 + q;
                float rg = sigmf(rv[q] + sb[c]);
                float z  = sigmf(zv[q] + sb[128 + c]);
                float nn = tanhf(nx[q] + sb[256 + c] + rg * nh[q]);
                out[q] = (1.f - z) * nn + z * mv[q];
            }
            if (ok){
                float4* dp = (float4*)(hdst + (size_t)gnode * HD + c0);
                dp[0] = make_float4(out[0], out[1], out[2], out[3]);
                dp[1] = make_float4(out[4], out[5], out[6], out[7]);
            }
        }
    }
}

// ---------------- out = h[index_map] ----------------
__global__ void k_gather(const int* __restrict__ imap, float* __restrict__ out){
    int i = blockIdx.x * blockDim.x + threadIdx.x;
    if (i < NN * HD){
        int node = i >> 7, c = i & 127;
        out[i] = g_h[(size_t)__ldg(&imap[node]) * HD + c];
    }
}

extern "C" void kernel_launch(void* const* d_in, const int* in_sizes, int n_in,
                              void* d_out, int out_size){
    const float* feats = (const float*)d_in[0];
    const float* wx    = (const float*)d_in[1];  // (256,1,384)
    const float* wh    = (const float*)d_in[2];  // (2,128,1,384)
    const float* bs    = (const float*)d_in[3];  // (2,1,384)
    const int*   esrc  = (const int*)  d_in[4];
    // d_in[5] edge_dst unused: dsts contiguous by construction (repeat, DEG=8)
    const int*   imap  = (const int*)  d_in[6];
    float*       out   = (float*)d_out;

    static bool attrDone = false;
    if (!attrDone){
        cudaFuncSetAttribute(k_fused, cudaFuncAttributeMaxDynamicSharedMemorySize, SMEM_DYN);
        attrDone = true;
    }

    void *px, *ph;
    cudaGetSymbolAddress(&px, g_x);
    cudaGetSymbolAddress(&ph, g_h);

    const int EW = NN * HD;
    k_prep   <<<(196608 + 255) / 256, 256>>>(wx, wh);
    k_zero_x <<<(EW + 255) / 256, 256>>>();
    k_scatter<<<(EW + 255) / 256, 256>>>(feats, imap);

    for (int layer = 0; layer < 2; layer++){
        const float* xs = (layer == 0) ? (const float*)px : (const float*)ph;
        const float* b  = bs + (size_t)layer * G3;
        for (int lvl = 0; lvl < NLVL; lvl++)
            k_fused<<<NCTA, NTHR, SMEM_DYN>>>(xs, (float*)ph, esrc, b, layer, lvl);
    }

    k_gather<<<(EW + 255) / 256, 256>>>(imap, out);
}

// round 4
// speedup vs baseline: 2.9336x; 1.2778x over previous
#include <cuda_runtime.h>
#include <cuda_bf16.h>
#include <stdint.h>
#include <math.h>

#define NN   200000
#define NPL  12500
#define NLVL 16
#define DEG  8
#define HD   128
#define G3   384
#define EPL  (NPL*DEG)

#define TM    64
#define NTHR  512
#define NCTA  ((NPL + TM - 1) / TM)   // 196

#define APITCH 272      // bytes per row of bf16 A tiles (128 bf16 + 8 pad)
#define MPITCH 136      // floats per row of m f32 tile (128 + 8 pad)

// dynamic smem layout (bytes)
#define OFF_AXH  0
#define OFF_AXL  17408
#define OFF_AMH  34816
#define OFF_AML  52224
#define OFF_MF   69632      // 64*136*4 = 34816
#define OFF_EDGE 104448     // 512 int
#define OFF_BIAS 106496     // 384 float
#define SMEM_DYN 108032

__device__ float    g_x[(size_t)NN*HD];
__device__ float    g_h[(size_t)NN*HD];
__device__ uint32_t g_bfrag[196608];   // [layer][g][part][kt(8)][nb(48)][lane(32)][j(2)]

// ---------------- helpers ----------------
__device__ __forceinline__ uint32_t smem_u32(const void* p){
    uint32_t a;
    asm("{ .reg .u64 t; cvta.to.shared.u64 t, %1; cvt.u32.u64 %0, t; }" : "=r"(a) : "l"(p));
    return a;
}
__device__ __forceinline__ void ldsm4(uint32_t* a, uint32_t addr){
    asm volatile("ldmatrix.sync.aligned.m8n8.x4.shared.b16 {%0,%1,%2,%3}, [%4];"
        : "=r"(a[0]), "=r"(a[1]), "=r"(a[2]), "=r"(a[3]) : "r"(addr));
}
__device__ __forceinline__ void mma_bf16(float* d, const uint32_t* a, uint32_t b0, uint32_t b1){
    asm volatile("mma.sync.aligned.m16n8k16.row.col.f32.bf16.bf16.f32 "
        "{%0,%1,%2,%3}, {%4,%5,%6,%7}, {%8,%9}, {%0,%1,%2,%3};"
        : "+f"(d[0]), "+f"(d[1]), "+f"(d[2]), "+f"(d[3])
        : "r"(a[0]), "r"(a[1]), "r"(a[2]), "r"(a[3]), "r"(b0), "r"(b1));
}
__device__ __forceinline__ float sigmf(float v){ return 1.f / (1.f + __expf(-v)); }
__device__ __forceinline__ float tanhfast(float v){ return 2.f / (1.f + __expf(-2.f * v)) - 1.f; }

// split 8 f32 -> hi/lo bf16, store as uint4 at padded (r, k0)
__device__ __forceinline__ void pack8(char* hi, char* lo, int r, int k0, float4 a, float4 b){
    float v[8] = {a.x, a.y, a.z, a.w, b.x, b.y, b.z, b.w};
    unsigned short hs[8], ls[8];
#pragma unroll
    for (int j = 0; j < 8; j++){
        __nv_bfloat16 h = __float2bfloat16(v[j]);
        __nv_bfloat16 l = __float2bfloat16(v[j] - __bfloat162float(h));
        hs[j] = __bfloat16_as_ushort(h);
        ls[j] = __bfloat16_as_ushort(l);
    }
    uint4 H, L;
    H.x = (uint32_t)hs[0] | ((uint32_t)hs[1] << 16);
    H.y = (uint32_t)hs[2] | ((uint32_t)hs[3] << 16);
    H.z = (uint32_t)hs[4] | ((uint32_t)hs[5] << 16);
    H.w = (uint32_t)hs[6] | ((uint32_t)hs[7] << 16);
    L.x = (uint32_t)ls[0] | ((uint32_t)ls[1] << 16);
    L.y = (uint32_t)ls[2] | ((uint32_t)ls[3] << 16);
    L.z = (uint32_t)ls[4] | ((uint32_t)ls[5] << 16);
    L.w = (uint32_t)ls[6] | ((uint32_t)ls[7] << 16);
    uint32_t o = (uint32_t)r * APITCH + (uint32_t)k0 * 2;
    *(uint4*)(hi + o) = H;
    *(uint4*)(lo + o) = L;
}

// ---------------- prep: weights -> bf16 hi/lo HMMA fragment arrays ----------------
__global__ void k_prep(const float* __restrict__ wx, const float* __restrict__ wh){
    int id = blockIdx.x * blockDim.x + threadIdx.x;
    if (id >= 196608) return;
    int pidx = id / 24576;                 // [layer(2)][g(2)][part(2)]
    int layer = pidx >> 2, g = (pidx >> 1) & 1, part = pidx & 1;
    int w = id % 24576;
    int kt = w / 3072;
    int rem = w % 3072;
    int nb = rem / 64;
    int rem2 = rem % 64;
    int lane = rem2 >> 1, j = rem2 & 1;
    int k = kt * 16 + (lane & 3) * 2 + 8 * j;
    int n = nb * 8 + (lane >> 2);
    const float* W = (g ? wh : wx) + (size_t)layer * HD * G3;
    float v0 = W[(size_t)k * G3 + n];
    float v1 = W[(size_t)(k + 1) * G3 + n];
    unsigned short p0, p1;
    __nv_bfloat16 h0 = __float2bfloat16(v0), h1 = __float2bfloat16(v1);
    if (part == 0){ p0 = __bfloat16_as_ushort(h0); p1 = __bfloat16_as_ushort(h1); }
    else {
        p0 = __bfloat16_as_ushort(__float2bfloat16(v0 - __bfloat162float(h0)));
        p1 = __bfloat16_as_ushort(__float2bfloat16(v1 - __bfloat162float(h1)));
    }
    g_bfrag[id] = (uint32_t)p0 | ((uint32_t)p1 << 16);
}

// ---------------- x = zeros.at[index_map].add(features) ----------------
__global__ void k_scatter4(const float4* __restrict__ f, const int* __restrict__ imap){
    int i = blockIdx.x * blockDim.x + threadIdx.x;
    if (i < NN * 32){
        int node = i >> 5, q = i & 31;
        float4 v = f[i];
        float* dst = g_x + (size_t)__ldg(&imap[node]) * HD + q * 4;
        atomicAdd(dst + 0, v.x);
        atomicAdd(dst + 1, v.y);
        atomicAdd(dst + 2, v.z);
        atomicAdd(dst + 3, v.w);
    }
}

// ---------------- fused level kernel: gather -> HMMA GEMMs -> GRU (reg epilogue) ----------------
__global__ void __launch_bounds__(NTHR, 1) k_fused(
    const float* __restrict__ xsrc,
    float* __restrict__ hdst,
    const int* __restrict__ esrc,
    const float* __restrict__ bias,
    int layer, int lvl)
{
    extern __shared__ char sm[];
    const uint32_t smb = smem_u32(sm);
    const int tid = threadIdx.x, warp = tid >> 5, lane = tid & 31;
    const int row0 = blockIdx.x * TM;
    const int s = lvl * NPL;
    const bool hasM = (lvl > 0);

    int*   se = (int*)  (sm + OFF_EDGE);
    float* sb = (float*)(sm + OFF_BIAS);
    float* MF = (float*)(sm + OFF_MF);

    if (hasM && tid < TM * DEG){
        int r = tid >> 3;
        int rr = (row0 + r < NPL) ? (row0 + r) : (NPL - 1);
        se[tid] = __ldg(&esrc[(size_t)(lvl - 1) * EPL + rr * DEG + (tid & 7)]);
    }
    if (tid < G3) sb[tid] = __ldg(&bias[tid]);
    __syncthreads();

    // build x A-tile (hi/lo bf16)
    for (int i = tid; i < TM * 16; i += NTHR){
        int r = i >> 4, k0 = (i & 15) * 8;
        int node = s + ((row0 + r < NPL) ? (row0 + r) : (NPL - 1));
        const float4* p = (const float4*)(xsrc + (size_t)node * HD + k0);
        pack8(sm + OFF_AXH, sm + OFF_AXL, r, k0, p[0], p[1]);
    }
    // build m A-tile (mean of 8 gathered h rows) + f32 copy for epilogue
    if (hasM){
        for (int i = tid; i < TM * 16; i += NTHR){
            int r = i >> 4, k0 = (i & 15) * 8;
            float4 s0 = make_float4(0.f, 0.f, 0.f, 0.f);
            float4 s1 = make_float4(0.f, 0.f, 0.f, 0.f);
#pragma unroll
            for (int e = 0; e < DEG; e++){
                int src = se[r * DEG + e];
                const float4* p = (const float4*)(hdst + (size_t)src * HD + k0);
                float4 v0 = p[0], v1 = p[1];
                s0.x += v0.x; s0.y += v0.y; s0.z += v0.z; s0.w += v0.w;
                s1.x += v1.x; s1.y += v1.y; s1.z += v1.z; s1.w += v1.w;
            }
            s0.x *= 0.125f; s0.y *= 0.125f; s0.z *= 0.125f; s0.w *= 0.125f;
            s1.x *= 0.125f; s1.y *= 0.125f; s1.z *= 0.125f; s1.w *= 0.125f;
            pack8(sm + OFF_AMH, sm + OFF_AML, r, k0, s0, s1);
            float* mp = MF + (size_t)r * MPITCH + k0;
            *(float4*)(mp)     = s0;
            *(float4*)(mp + 4) = s1;
        }
    }
    __syncthreads();

    // -------- register-accumulated GEMMs --------
    // warp w owns cols {8w, 128+8w, 256+8w}: accX[rb][g] holds gate g (r,z get Cx+Ch summed,
    // n holds Cx only); accH[rb] holds Ch for the n gate.
    float accX[4][3][4];
    float accH[4][4];
#pragma unroll
    for (int rb = 0; rb < 4; rb++){
#pragma unroll
        for (int g = 0; g < 3; g++)
#pragma unroll
            for (int q = 0; q < 4; q++) accX[rb][g][q] = 0.f;
#pragma unroll
        for (int q = 0; q < 4; q++) accH[rb][q] = 0.f;
    }

    const uint32_t aXh = smb + OFF_AXH, aXl = smb + OFF_AXL;
    const uint32_t aMh = smb + OFF_AMH, aMl = smb + OFF_AML;
    const uint32_t laneOff = (uint32_t)(lane & 15) * APITCH + (uint32_t)((lane >> 4) << 4);

    const uint32_t* Bx_hi = g_bfrag + (size_t)((layer * 2 + 0) * 2 + 0) * 24576;
    const uint32_t* Bx_lo = g_bfrag + (size_t)((layer * 2 + 0) * 2 + 1) * 24576;
    const uint32_t* Bh_hi = g_bfrag + (size_t)((layer * 2 + 1) * 2 + 0) * 24576;
    const uint32_t* Bh_lo = g_bfrag + (size_t)((layer * 2 + 1) * 2 + 1) * 24576;

#pragma unroll 2
    for (int kt = 0; kt < 8; kt++){
        const size_t bbase = (size_t)kt * 3072 + (size_t)lane * 2;
        // Wx pass
        {
            uint2 BH[3], BL[3];
#pragma unroll
            for (int g = 0; g < 3; g++){
                size_t idx = bbase + (size_t)(16 * g + warp) * 64;
                BH[g] = *(const uint2*)(Bx_hi + idx);
                BL[g] = *(const uint2*)(Bx_lo + idx);
            }
#pragma unroll
            for (int rb = 0; rb < 4; rb++){
                uint32_t ah[4], al[4];
                uint32_t ao = laneOff + (uint32_t)rb * 16 * APITCH + (uint32_t)kt * 32;
                ldsm4(ah, aXh + ao);
                ldsm4(al, aXl + ao);
#pragma unroll
                for (int g = 0; g < 3; g++){
                    mma_bf16(accX[rb][g], ah, BH[g].x, BH[g].y);
                    mma_bf16(accX[rb][g], al, BH[g].x, BH[g].y);
                    mma_bf16(accX[rb][g], ah, BL[g].x, BL[g].y);
                }
            }
        }
        // Wh pass (m)
        if (hasM){
            uint2 BH[3], BL[3];
#pragma unroll
            for (int g = 0; g < 3; g++){
                size_t idx = bbase + (size_t)(16 * g + warp) * 64;
                BH[g] = *(const uint2*)(Bh_hi + idx);
                BL[g] = *(const uint2*)(Bh_lo + idx);
            }
#pragma unroll
            for (int rb = 0; rb < 4; rb++){
                uint32_t mh[4], ml[4];
                uint32_t ao = laneOff + (uint32_t)rb * 16 * APITCH + (uint32_t)kt * 32;
                ldsm4(mh, aMh + ao);
                ldsm4(ml, aMl + ao);
#pragma unroll
                for (int g = 0; g < 2; g++){
                    mma_bf16(accX[rb][g], mh, BH[g].x, BH[g].y);
                    mma_bf16(accX[rb][g], ml, BH[g].x, BH[g].y);
                    mma_bf16(accX[rb][g], mh, BL[g].x, BL[g].y);
                }
                mma_bf16(accH[rb], mh, BH[2].x, BH[2].y);
                mma_bf16(accH[rb], ml, BH[2].x, BH[2].y);
                mma_bf16(accH[rb], mh, BL[2].x, BL[2].y);
            }
        }
    }

    // -------- register epilogue --------
    const int c0 = warp * 8 + (lane & 3) * 2;
    const float br0 = sb[c0],       br1 = sb[c0 + 1];
    const float bz0 = sb[128 + c0], bz1 = sb[128 + c0 + 1];
    const float bn0 = sb[256 + c0], bn1 = sb[256 + c0 + 1];

#pragma unroll
    for (int rb = 0; rb < 4; rb++){
#pragma unroll
        for (int half = 0; half < 2; half++){
            const int row = rb * 16 + (lane >> 2) + half * 8;
            const int nl  = row0 + row;
            const int q0  = half * 2;
            float mv0 = 0.f, mv1 = 0.f, gh0 = 0.f, gh1 = 0.f;
            if (hasM){
                float2 mp = *(const float2*)(MF + (size_t)row * MPITCH + c0);
                mv0 = mp.x; mv1 = mp.y;
                gh0 = accH[rb][q0]; gh1 = accH[rb][q0 + 1];
            }
            float r0 = sigmf(accX[rb][0][q0]     + br0);
            float r1 = sigmf(accX[rb][0][q0 + 1] + br1);
            float z0 = sigmf(accX[rb][1][q0]     + bz0);
            float z1 = sigmf(accX[rb][1][q0 + 1] + bz1);
            float n0 = tanhfast(accX[rb][2][q0]     + bn0 + r0 * gh0);
            float n1 = tanhfast(accX[rb][2][q0 + 1] + bn1 + r1 * gh1);
            float o0 = (1.f - z0) * n0 + z0 * mv0;
            float o1 = (1.f - z1) * n1 + z1 * mv1;
            if (nl < NPL)
                *(float2*)(hdst + (size_t)(s + nl) * HD + c0) = make_float2(o0, o1);
        }
    }
}

// ---------------- out = h[index_map] ----------------
__global__ void k_gather4(const int* __restrict__ imap, float4* __restrict__ out){
    int i = blockIdx.x * blockDim.x + threadIdx.x;
    if (i < NN * 32){
        int node = i >> 5, q = i & 31;
        out[i] = *(const float4*)(g_h + (size_t)__ldg(&imap[node]) * HD + q * 4);
    }
}

extern "C" void kernel_launch(void* const* d_in, const int* in_sizes, int n_in,
                              void* d_out, int out_size){
    const float* feats = (const float*)d_in[0];
    const float* wx    = (const float*)d_in[1];  // (256,1,384)
    const float* wh    = (const float*)d_in[2];  // (2,128,1,384)
    const float* bs    = (const float*)d_in[3];  // (2,1,384)
    const int*   esrc  = (const int*)  d_in[4];
    // d_in[5] edge_dst unused: dsts contiguous by construction (repeat, DEG=8)
    const int*   imap  = (const int*)  d_in[6];
    float*       out   = (float*)d_out;

    cudaFuncSetAttribute(k_fused, cudaFuncAttributeMaxDynamicSharedMemorySize, SMEM_DYN);

    void *px, *ph;
    cudaGetSymbolAddress(&px, g_x);
    cudaGetSymbolAddress(&ph, g_h);

    const int EV = NN * 32;  // float4 elements
    k_prep<<<(196608 + 255) / 256, 256>>>(wx, wh);
    cudaMemsetAsync(px, 0, (size_t)NN * HD * sizeof(float));
    k_scatter4<<<(EV + 255) / 256, 256>>>((const float4*)feats, imap);

    for (int layer = 0; layer < 2; layer++){
        const float* xs = (layer == 0) ? (const float*)px : (const float*)ph;
        const float* b  = bs + (size_t)layer * G3;
        for (int lvl = 0; lvl < NLVL; lvl++)
            k_fused<<<NCTA, NTHR, SMEM_DYN>>>(xs, (float*)ph, esrc, b, layer, lvl);
    }

    k_gather4<<<(EV + 255) / 256, 256>>>(imap, (float4*)out);
}

// round 5
// speedup vs baseline: 3.4005x; 1.1592x over previous
#include <cuda_runtime.h>
#include <cuda_bf16.h>
#include <stdint.h>
#include <math.h>

#define NN   200000
#define NPL  12500
#define NLVL 16
#define DEG  8
#define HD   128
#define G3   384
#define EPL  (NPL*DEG)

#define APITCH 272        // bytes per bf16 A-tile row (128 bf16 + 8 pad)

#define GX_TM  64
#define GX_NT  512
#define GX_NCTA (NN / GX_TM)          // 3125

#define LV_TM  32
#define LV_NT  256
#define LV_NCTA ((NPL + LV_TM - 1) / LV_TM)   // 391

__device__ float    g_x [(size_t)NN*HD];
__device__ float    g_h [(size_t)NN*HD];
__device__ float    g_gx[(size_t)NN*G3];
__device__ uint32_t g_bfrag[196608];   // [layer][g][part][kt(8)][nb(48)][lane(32)][j(2)]

// ---------------- helpers ----------------
__device__ __forceinline__ uint32_t smem_u32(const void* p){
    uint32_t a;
    asm("{ .reg .u64 t; cvta.to.shared.u64 t, %1; cvt.u32.u64 %0, t; }" : "=r"(a) : "l"(p));
    return a;
}
__device__ __forceinline__ void ldsm4(uint32_t* a, uint32_t addr){
    asm volatile("ldmatrix.sync.aligned.m8n8.x4.shared.b16 {%0,%1,%2,%3}, [%4];"
        : "=r"(a[0]), "=r"(a[1]), "=r"(a[2]), "=r"(a[3]) : "r"(addr));
}
__device__ __forceinline__ void mma_bf16(float* d, const uint32_t* a, uint32_t b0, uint32_t b1){
    asm volatile("mma.sync.aligned.m16n8k16.row.col.f32.bf16.bf16.f32 "
        "{%0,%1,%2,%3}, {%4,%5,%6,%7}, {%8,%9}, {%0,%1,%2,%3};"
        : "+f"(d[0]), "+f"(d[1]), "+f"(d[2]), "+f"(d[3])
        : "r"(a[0]), "r"(a[1]), "r"(a[2]), "r"(a[3]), "r"(b0), "r"(b1));
}
__device__ __forceinline__ float sigmf(float v){ return 1.f / (1.f + __expf(-v)); }
__device__ __forceinline__ float tanhfast(float v){ return 2.f / (1.f + __expf(-2.f * v)) - 1.f; }
__device__ __forceinline__ float bflo(uint32_t u){ return __bfloat162float(__ushort_as_bfloat16((unsigned short)(u & 0xFFFF))); }
__device__ __forceinline__ float bfhi(uint32_t u){ return __bfloat162float(__ushort_as_bfloat16((unsigned short)(u >> 16))); }

// split 8 f32 -> hi/lo bf16, store as uint4 at padded (r, k0)
__device__ __forceinline__ void pack8(char* hi, char* lo, int r, int k0, float4 a, float4 b){
    float v[8] = {a.x, a.y, a.z, a.w, b.x, b.y, b.z, b.w};
    unsigned short hs[8], ls[8];
#pragma unroll
    for (int j = 0; j < 8; j++){
        __nv_bfloat16 h = __float2bfloat16(v[j]);
        __nv_bfloat16 l = __float2bfloat16(v[j] - __bfloat162float(h));
        hs[j] = __bfloat16_as_ushort(h);
        ls[j] = __bfloat16_as_ushort(l);
    }
    uint4 H, L;
    H.x = (uint32_t)hs[0] | ((uint32_t)hs[1] << 16);
    H.y = (uint32_t)hs[2] | ((uint32_t)hs[3] << 16);
    H.z = (uint32_t)hs[4] | ((uint32_t)hs[5] << 16);
    H.w = (uint32_t)hs[6] | ((uint32_t)hs[7] << 16);
    L.x = (uint32_t)ls[0] | ((uint32_t)ls[1] << 16);
    L.y = (uint32_t)ls[2] | ((uint32_t)ls[3] << 16);
    L.z = (uint32_t)ls[4] | ((uint32_t)ls[5] << 16);
    L.w = (uint32_t)ls[6] | ((uint32_t)ls[7] << 16);
    uint32_t o = (uint32_t)r * APITCH + (uint32_t)k0 * 2;
    *(uint4*)(hi + o) = H;
    *(uint4*)(lo + o) = L;
}

// ---------------- prep: weights -> bf16 hi/lo HMMA fragment arrays ----------------
__global__ void k_prep(const float* __restrict__ wx, const float* __restrict__ wh){
    int id = blockIdx.x * blockDim.x + threadIdx.x;
    if (id >= 196608) return;
    int pidx = id / 24576;                 // [layer(2)][g(2)][part(2)]
    int layer = pidx >> 2, g = (pidx >> 1) & 1, part = pidx & 1;
    int w = id % 24576;
    int kt = w / 3072;
    int rem = w % 3072;
    int nb = rem / 64;
    int rem2 = rem % 64;
    int lane = rem2 >> 1, j = rem2 & 1;
    int k = kt * 16 + (lane & 3) * 2 + 8 * j;
    int n = nb * 8 + (lane >> 2);
    const float* W = (g ? wh : wx) + (size_t)layer * HD * G3;
    float v0 = W[(size_t)k * G3 + n];
    float v1 = W[(size_t)(k + 1) * G3 + n];
    unsigned short p0, p1;
    __nv_bfloat16 h0 = __float2bfloat16(v0), h1 = __float2bfloat16(v1);
    if (part == 0){ p0 = __bfloat16_as_ushort(h0); p1 = __bfloat16_as_ushort(h1); }
    else {
        p0 = __bfloat16_as_ushort(__float2bfloat16(v0 - __bfloat162float(h0)));
        p1 = __bfloat16_as_ushort(__float2bfloat16(v1 - __bfloat162float(h1)));
    }
    g_bfrag[id] = (uint32_t)p0 | ((uint32_t)p1 << 16);
}

// ---------------- x = zeros.at[index_map].add(features) ----------------
__global__ void k_scatter4(const float4* __restrict__ f, const int* __restrict__ imap){
    int i = blockIdx.x * blockDim.x + threadIdx.x;
    if (i < NN * 32){
        int node = i >> 5, q = i & 31;
        float4 v = f[i];
        float* dst = g_x + (size_t)__ldg(&imap[node]) * HD + q * 4;
        atomicAdd(dst + 0, v.x);
        atomicAdd(dst + 1, v.y);
        atomicAdd(dst + 2, v.z);
        atomicAdd(dst + 3, v.w);
    }
}

// ---------------- big GEMM: gx = A[NN,128] @ Wx[128,384] + b (3-pass bf16 HMMA) --------
__global__ void __launch_bounds__(GX_NT, 1) k_gx(
    const float* __restrict__ xsrc, const float* __restrict__ bias, int layer)
{
    __shared__ char sAH[GX_TM * APITCH];   // 17408
    __shared__ char sAL[GX_TM * APITCH];
    const int tid = threadIdx.x, warp = tid >> 5, lane = tid & 31;
    const int row0 = blockIdx.x * GX_TM;

    for (int i = tid; i < GX_TM * 16; i += GX_NT){
        int r = i >> 4, k0 = (i & 15) * 8;
        const float4* p = (const float4*)(xsrc + (size_t)(row0 + r) * HD + k0);
        pack8(sAH, sAL, r, k0, p[0], p[1]);
    }
    __syncthreads();

    float acc[4][3][4];
#pragma unroll
    for (int rb = 0; rb < 4; rb++)
#pragma unroll
        for (int nb = 0; nb < 3; nb++)
#pragma unroll
            for (int q = 0; q < 4; q++) acc[rb][nb][q] = 0.f;

    const uint32_t aH = smem_u32(sAH), aL = smem_u32(sAL);
    const uint32_t laneOff = (uint32_t)(lane & 15) * APITCH + (uint32_t)((lane >> 4) << 4);
    const uint32_t* B_hi = g_bfrag + (size_t)((layer * 2 + 0) * 2 + 0) * 24576;
    const uint32_t* B_lo = g_bfrag + (size_t)((layer * 2 + 0) * 2 + 1) * 24576;

#pragma unroll 2
    for (int kt = 0; kt < 8; kt++){
        uint2 BH[3], BL[3];
#pragma unroll
        for (int nbi = 0; nbi < 3; nbi++){
            size_t idx = (size_t)kt * 3072 + (size_t)(3 * warp + nbi) * 64 + (size_t)lane * 2;
            BH[nbi] = *(const uint2*)(B_hi + idx);
            BL[nbi] = *(const uint2*)(B_lo + idx);
        }
#pragma unroll
        for (int rb = 0; rb < 4; rb++){
            uint32_t ah[4], al[4];
            uint32_t ao = laneOff + (uint32_t)rb * 16 * APITCH + (uint32_t)kt * 32;
            ldsm4(ah, aH + ao);
            ldsm4(al, aL + ao);
#pragma unroll
            for (int nbi = 0; nbi < 3; nbi++){
                mma_bf16(acc[rb][nbi], ah, BH[nbi].x, BH[nbi].y);
                mma_bf16(acc[rb][nbi], al, BH[nbi].x, BH[nbi].y);
                mma_bf16(acc[rb][nbi], ah, BL[nbi].x, BL[nbi].y);
            }
        }
    }

    const int cb = warp * 24 + (lane & 3) * 2;
    float2 bv[3];
#pragma unroll
    for (int nbi = 0; nbi < 3; nbi++)
        bv[nbi] = *(const float2*)(bias + cb + nbi * 8);

#pragma unroll
    for (int rb = 0; rb < 4; rb++){
#pragma unroll
        for (int half = 0; half < 2; half++){
            int row = rb * 16 + (lane >> 2) + half * 8;
            float* gp = g_gx + (size_t)(row0 + row) * G3;
            int q0 = half * 2;
#pragma unroll
            for (int nbi = 0; nbi < 3; nbi++){
                *(float2*)(gp + cb + nbi * 8) =
                    make_float2(acc[rb][nbi][q0] + bv[nbi].x, acc[rb][nbi][q0 + 1] + bv[nbi].y);
            }
        }
    }
}

// ---------------- level 0: h = (1-z)*tanh(gn) ----------------
__global__ void k_level0(){
    int i = blockIdx.x * blockDim.x + threadIdx.x;
    if (i < NPL * 32){
        int node = i >> 5, c = (i & 31) * 4;
        const float* gp = g_gx + (size_t)node * G3;
        float4 z4 = *(const float4*)(gp + 128 + c);
        float4 n4 = *(const float4*)(gp + 256 + c);
        float4 o;
        o.x = (1.f - sigmf(z4.x)) * tanhfast(n4.x);
        o.y = (1.f - sigmf(z4.y)) * tanhfast(n4.y);
        o.z = (1.f - sigmf(z4.z)) * tanhfast(n4.z);
        o.w = (1.f - sigmf(z4.w)) * tanhfast(n4.w);
        *(float4*)(g_h + (size_t)node * HD + c) = o;
    }
}

// ---------------- level kernel: gather mean -> m@Wh (HMMA) -> GRU gates ----------------
__global__ void __launch_bounds__(LV_NT, 4) k_level(
    const int* __restrict__ esrc, int layer, int lvl)
{
    __shared__ int  se[LV_TM * DEG];         // 1024 B
    __shared__ char sMH[LV_TM * APITCH];     // 8704 B
    __shared__ char sML[LV_TM * APITCH];     // 8704 B

    const int tid = threadIdx.x, warp = tid >> 5, lane = tid & 31;
    const int row0 = blockIdx.x * LV_TM;
    const int s = lvl * NPL;

    // stage edges (exactly 256)
    {
        int r = tid >> 3;
        int rr = (row0 + r < NPL) ? (row0 + r) : (NPL - 1);
        se[tid] = __ldg(&esrc[(size_t)(lvl - 1) * EPL + rr * DEG + (tid & 7)]);
    }
    __syncthreads();

    // gather mean of 8 h-rows, pack hi/lo bf16
    for (int i = tid; i < LV_TM * 16; i += LV_NT){
        int r = i >> 4, k0 = (i & 15) * 8;
        float4 s0 = make_float4(0.f, 0.f, 0.f, 0.f);
        float4 s1 = make_float4(0.f, 0.f, 0.f, 0.f);
#pragma unroll
        for (int e = 0; e < DEG; e++){
            const float4* p = (const float4*)(g_h + (size_t)se[r * DEG + e] * HD + k0);
            float4 v0 = p[0], v1 = p[1];
            s0.x += v0.x; s0.y += v0.y; s0.z += v0.z; s0.w += v0.w;
            s1.x += v1.x; s1.y += v1.y; s1.z += v1.z; s1.w += v1.w;
        }
        s0.x *= 0.125f; s0.y *= 0.125f; s0.z *= 0.125f; s0.w *= 0.125f;
        s1.x *= 0.125f; s1.y *= 0.125f; s1.z *= 0.125f; s1.w *= 0.125f;
        pack8(sMH, sML, r, k0, s0, s1);
    }
    __syncthreads();

    const uint32_t aH = smem_u32(sMH), aL = smem_u32(sML);
    const uint32_t laneOff = (uint32_t)(lane & 15) * APITCH + (uint32_t)((lane >> 4) << 4);
    const uint32_t* B_hi = g_bfrag + (size_t)((layer * 2 + 1) * 2 + 0) * 24576;
    const uint32_t* B_lo = g_bfrag + (size_t)((layer * 2 + 1) * 2 + 1) * 24576;

#pragma unroll
    for (int j = 0; j < 2; j++){
        float acc[2][3][4];
#pragma unroll
        for (int rb = 0; rb < 2; rb++)
#pragma unroll
            for (int g = 0; g < 3; g++)
#pragma unroll
                for (int q = 0; q < 4; q++) acc[rb][g][q] = 0.f;

#pragma unroll 2
        for (int kt = 0; kt < 8; kt++){
            uint2 BH[3], BL[3];
#pragma unroll
            for (int g = 0; g < 3; g++){
                size_t idx = (size_t)kt * 3072 + (size_t)(16 * g + 2 * warp + j) * 64 + (size_t)lane * 2;
                BH[g] = *(const uint2*)(B_hi + idx);
                BL[g] = *(const uint2*)(B_lo + idx);
            }
#pragma unroll
            for (int rb = 0; rb < 2; rb++){
                uint32_t mh[4], ml[4];
                uint32_t ao = laneOff + (uint32_t)rb * 16 * APITCH + (uint32_t)kt * 32;
                ldsm4(mh, aH + ao);
                ldsm4(ml, aL + ao);
#pragma unroll
                for (int g = 0; g < 3; g++){
                    mma_bf16(acc[rb][g], mh, BH[g].x, BH[g].y);
                    mma_bf16(acc[rb][g], ml, BH[g].x, BH[g].y);
                    mma_bf16(acc[rb][g], mh, BL[g].x, BL[g].y);
                }
            }
        }

        // epilogue for this col-group
        const int c0 = warp * 16 + j * 8 + (lane & 3) * 2;
#pragma unroll
        for (int rb = 0; rb < 2; rb++){
#pragma unroll
            for (int half = 0; half < 2; half++){
                int row = rb * 16 + (lane >> 2) + half * 8;
                int nl = row0 + row;
                if (nl < NPL){
                    int node = s + nl;
                    const float* gp = g_gx + (size_t)node * G3;
                    float2 gr = *(const float2*)(gp + c0);
                    float2 gz = *(const float2*)(gp + 128 + c0);
                    float2 gn = *(const float2*)(gp + 256 + c0);
                    uint32_t o = (uint32_t)row * APITCH + (uint32_t)c0 * 2;
                    uint32_t Hm = *(const uint32_t*)(sMH + o);
                    uint32_t Lm = *(const uint32_t*)(sML + o);
                    float mv0 = bflo(Hm) + bflo(Lm);
                    float mv1 = bfhi(Hm) + bfhi(Lm);
                    int q0 = half * 2;
                    float r0 = sigmf(gr.x + acc[rb][0][q0]);
                    float r1 = sigmf(gr.y + acc[rb][0][q0 + 1]);
                    float z0 = sigmf(gz.x + acc[rb][1][q0]);
                    float z1 = sigmf(gz.y + acc[rb][1][q0 + 1]);
                    float n0 = tanhfast(gn.x + r0 * acc[rb][2][q0]);
                    float n1 = tanhfast(gn.y + r1 * acc[rb][2][q0 + 1]);
                    *(float2*)(g_h + (size_t)node * HD + c0) =
                        make_float2((1.f - z0) * n0 + z0 * mv0,
                                    (1.f - z1) * n1 + z1 * mv1);
                }
            }
        }
    }
}

// ---------------- out = h[index_map] ----------------
__global__ void k_gather4(const int* __restrict__ imap, float4* __restrict__ out){
    int i = blockIdx.x * blockDim.x + threadIdx.x;
    if (i < NN * 32){
        int node = i >> 5, q = i & 31;
        out[i] = *(const float4*)(g_h + (size_t)__ldg(&imap[node]) * HD + q * 4);
    }
}

extern "C" void kernel_launch(void* const* d_in, const int* in_sizes, int n_in,
                              void* d_out, int out_size){
    const float* feats = (const float*)d_in[0];
    const float* wx    = (const float*)d_in[1];  // (256,1,384)
    const float* wh    = (const float*)d_in[2];  // (2,128,1,384)
    const float* bs    = (const float*)d_in[3];  // (2,1,384)
    const int*   esrc  = (const int*)  d_in[4];
    // d_in[5] edge_dst unused: dsts contiguous by construction (repeat, DEG=8)
    const int*   imap  = (const int*)  d_in[6];
    float*       out   = (float*)d_out;

    void *px, *ph;
    cudaGetSymbolAddress(&px, g_x);
    cudaGetSymbolAddress(&ph, g_h);

    const int EV = NN * 32;  // float4 elements
    k_prep<<<(196608 + 255) / 256, 256>>>(wx, wh);
    cudaMemsetAsync(px, 0, (size_t)NN * HD * sizeof(float));
    k_scatter4<<<(EV + 255) / 256, 256>>>((const float4*)feats, imap);

    for (int layer = 0; layer < 2; layer++){
        const float* xs = (layer == 0) ? (const float*)px : (const float*)ph;
        k_gx<<<GX_NCTA, GX_NT>>>(xs, bs + (size_t)layer * G3, layer);
        k_level0<<<(NPL * 32 + 255) / 256, 256>>>();
        for (int lvl = 1; lvl < NLVL; lvl++)
            k_level<<<LV_NCTA, LV_NT>>>(esrc, layer, lvl);
    }

    k_gather4<<<(EV + 255) / 256, 256>>>(imap, (float4*)out);
}

// round 6
// speedup vs baseline: 4.0245x; 1.1835x over previous
#include <cuda_runtime.h>
#include <cuda_bf16.h>
#include <stdint.h>
#include <math.h>

#define NN   200000
#define NPL  12500
#define NLVL 16
#define DEG  8
#define HD   128
#define G3   384
#define EPL  (NPL*DEG)

#define APITCH 272        // bytes per bf16 A-tile row (128 bf16 + 8 pad)

#define LV_TM  32
#define LV_NT  256
#define LV_NCTA ((NPL + LV_TM - 1) / LV_TM)   // 391

__device__ float    g_x[(size_t)NN*HD];
__device__ float    g_h[(size_t)NN*HD];
__device__ uint32_t g_bfrag[196608];   // [layer][g][part][kt(8)][nb(48)][lane(32)][j(2)]

// ---------------- helpers ----------------
__device__ __forceinline__ uint32_t smem_u32(const void* p){
    uint32_t a;
    asm("{ .reg .u64 t; cvta.to.shared.u64 t, %1; cvt.u32.u64 %0, t; }" : "=r"(a) : "l"(p));
    return a;
}
__device__ __forceinline__ void ldsm4(uint32_t* a, uint32_t addr){
    asm volatile("ldmatrix.sync.aligned.m8n8.x4.shared.b16 {%0,%1,%2,%3}, [%4];"
        : "=r"(a[0]), "=r"(a[1]), "=r"(a[2]), "=r"(a[3]) : "r"(addr));
}
__device__ __forceinline__ void mma_bf16(float* d, const uint32_t* a, uint32_t b0, uint32_t b1){
    asm volatile("mma.sync.aligned.m16n8k16.row.col.f32.bf16.bf16.f32 "
        "{%0,%1,%2,%3}, {%4,%5,%6,%7}, {%8,%9}, {%0,%1,%2,%3};"
        : "+f"(d[0]), "+f"(d[1]), "+f"(d[2]), "+f"(d[3])
        : "r"(a[0]), "r"(a[1]), "r"(a[2]), "r"(a[3]), "r"(b0), "r"(b1));
}
__device__ __forceinline__ float sigmf(float v){ return 1.f / (1.f + __expf(-v)); }
__device__ __forceinline__ float tanhfast(float v){ return 2.f / (1.f + __expf(-2.f * v)) - 1.f; }
__device__ __forceinline__ float bflo(uint32_t u){ return __bfloat162float(__ushort_as_bfloat16((unsigned short)(u & 0xFFFF))); }
__device__ __forceinline__ float bfhi(uint32_t u){ return __bfloat162float(__ushort_as_bfloat16((unsigned short)(u >> 16))); }

// split 8 f32 -> hi/lo bf16, store as uint4 at padded (r, k0)
__device__ __forceinline__ void pack8(char* hi, char* lo, int r, int k0, float4 a, float4 b){
    float v[8] = {a.x, a.y, a.z, a.w, b.x, b.y, b.z, b.w};
    unsigned short hs[8], ls[8];
#pragma unroll
    for (int j = 0; j < 8; j++){
        __nv_bfloat16 h = __float2bfloat16(v[j]);
        __nv_bfloat16 l = __float2bfloat16(v[j] - __bfloat162float(h));
        hs[j] = __bfloat16_as_ushort(h);
        ls[j] = __bfloat16_as_ushort(l);
    }
    uint4 H, L;
    H.x = (uint32_t)hs[0] | ((uint32_t)hs[1] << 16);
    H.y = (uint32_t)hs[2] | ((uint32_t)hs[3] << 16);
    H.z = (uint32_t)hs[4] | ((uint32_t)hs[5] << 16);
    H.w = (uint32_t)hs[6] | ((uint32_t)hs[7] << 16);
    L.x = (uint32_t)ls[0] | ((uint32_t)ls[1] << 16);
    L.y = (uint32_t)ls[2] | ((uint32_t)ls[3] << 16);
    L.z = (uint32_t)ls[4] | ((uint32_t)ls[5] << 16);
    L.w = (uint32_t)ls[6] | ((uint32_t)ls[7] << 16);
    uint32_t o = (uint32_t)r * APITCH + (uint32_t)k0 * 2;
    *(uint4*)(hi + o) = H;
    *(uint4*)(lo + o) = L;
}

// ---------------- prep: weights -> bf16 hi/lo HMMA fragment arrays ----------------
__global__ void k_prep(const float* __restrict__ wx, const float* __restrict__ wh){
    int id = blockIdx.x * blockDim.x + threadIdx.x;
    if (id >= 196608) return;
    int pidx = id / 24576;                 // [layer(2)][g(2)][part(2)]
    int layer = pidx >> 2, g = (pidx >> 1) & 1, part = pidx & 1;
    int w = id % 24576;
    int kt = w / 3072;
    int rem = w % 3072;
    int nb = rem / 64;
    int rem2 = rem % 64;
    int lane = rem2 >> 1, j = rem2 & 1;
    int k = kt * 16 + (lane & 3) * 2 + 8 * j;
    int n = nb * 8 + (lane >> 2);
    const float* W = (g ? wh : wx) + (size_t)layer * HD * G3;
    float v0 = W[(size_t)k * G3 + n];
    float v1 = W[(size_t)(k + 1) * G3 + n];
    unsigned short p0, p1;
    __nv_bfloat16 h0 = __float2bfloat16(v0), h1 = __float2bfloat16(v1);
    if (part == 0){ p0 = __bfloat16_as_ushort(h0); p1 = __bfloat16_as_ushort(h1); }
    else {
        p0 = __bfloat16_as_ushort(__float2bfloat16(v0 - __bfloat162float(h0)));
        p1 = __bfloat16_as_ushort(__float2bfloat16(v1 - __bfloat162float(h1)));
    }
    g_bfrag[id] = (uint32_t)p0 | ((uint32_t)p1 << 16);
}

// ---------------- x = zeros.at[index_map].add(features): permutation -> plain store ----
__global__ void k_scatter4(const float4* __restrict__ f, const int* __restrict__ imap){
    int i = blockIdx.x * blockDim.x + threadIdx.x;
    if (i < NN * 32){
        int node = i >> 5, q = i & 31;
        *(float4*)(g_x + (size_t)__ldg(&imap[node]) * HD + q * 4) = f[i];
    }
}

// ---------------- fused level kernel: x-GEMM + gather mean + m-GEMM + GRU ----------------
__global__ void __launch_bounds__(LV_NT, 3) k_lv(
    const float* __restrict__ xsrc,
    float* __restrict__ hdst,
    const int* __restrict__ esrc,
    const float* __restrict__ bias,
    int layer, int lvl)
{
    __shared__ int   se[LV_TM * DEG];        // 1 KB
    __shared__ float sb[G3];                 // 1.5 KB
    __shared__ char  sXH[LV_TM * APITCH];    // 8.5 KB
    __shared__ char  sXL[LV_TM * APITCH];
    __shared__ char  sMH[LV_TM * APITCH];
    __shared__ char  sML[LV_TM * APITCH];

    const int tid = threadIdx.x, warp = tid >> 5, lane = tid & 31;
    const int row0 = blockIdx.x * LV_TM;
    const int s = lvl * NPL;
    const bool hasM = (lvl > 0);

    if (hasM){
        int r = tid >> 3;
        int rr = (row0 + r < NPL) ? (row0 + r) : (NPL - 1);
        se[tid] = __ldg(&esrc[(size_t)(lvl - 1) * EPL + rr * DEG + (tid & 7)]);
    }
    if (tid < G3 / 2) *(float2*)(sb + tid * 2) = *(const float2*)(bias + tid * 2);
    __syncthreads();

    // pack x A-tile
    for (int i = tid; i < LV_TM * 16; i += LV_NT){
        int r = i >> 4, k0 = (i & 15) * 8;
        int node = s + ((row0 + r < NPL) ? (row0 + r) : (NPL - 1));
        const float4* p = (const float4*)(xsrc + (size_t)node * HD + k0);
        pack8(sXH, sXL, r, k0, p[0], p[1]);
    }
    // gather mean -> pack m A-tile
    if (hasM){
        for (int i = tid; i < LV_TM * 16; i += LV_NT){
            int r = i >> 4, k0 = (i & 15) * 8;
            float4 s0 = make_float4(0.f, 0.f, 0.f, 0.f);
            float4 s1 = make_float4(0.f, 0.f, 0.f, 0.f);
#pragma unroll
            for (int e = 0; e < DEG; e++){
                const float4* p = (const float4*)(hdst + (size_t)se[r * DEG + e] * HD + k0);
                float4 v0 = p[0], v1 = p[1];
                s0.x += v0.x; s0.y += v0.y; s0.z += v0.z; s0.w += v0.w;
                s1.x += v1.x; s1.y += v1.y; s1.z += v1.z; s1.w += v1.w;
            }
            s0.x *= 0.125f; s0.y *= 0.125f; s0.z *= 0.125f; s0.w *= 0.125f;
            s1.x *= 0.125f; s1.y *= 0.125f; s1.z *= 0.125f; s1.w *= 0.125f;
            pack8(sMH, sML, r, k0, s0, s1);
        }
    }
    __syncthreads();

    const uint32_t xH = smem_u32(sXH), xL = smem_u32(sXL);
    const uint32_t mH = smem_u32(sMH), mL = smem_u32(sML);
    const uint32_t laneOff = (uint32_t)(lane & 15) * APITCH + (uint32_t)((lane >> 4) << 4);
    const uint32_t* Bx_hi = g_bfrag + (size_t)((layer * 2 + 0) * 2 + 0) * 24576;
    const uint32_t* Bx_lo = g_bfrag + (size_t)((layer * 2 + 0) * 2 + 1) * 24576;
    const uint32_t* Bh_hi = g_bfrag + (size_t)((layer * 2 + 1) * 2 + 0) * 24576;
    const uint32_t* Bh_lo = g_bfrag + (size_t)((layer * 2 + 1) * 2 + 1) * 24576;

#pragma unroll
    for (int j = 0; j < 2; j++){
        // acc gates: 0 = r (Cx+Ch), 1 = z (Cx+Ch), 2 = n_x, 3 = n_h
        float acc[2][4][4];
#pragma unroll
        for (int rb = 0; rb < 2; rb++)
#pragma unroll
            for (int g = 0; g < 4; g++)
#pragma unroll
                for (int q = 0; q < 4; q++) acc[rb][g][q] = 0.f;

        const int nbBase = 2 * warp + j;
#pragma unroll 2
        for (int kt = 0; kt < 8; kt++){
            const size_t bb = (size_t)kt * 3072 + (size_t)lane * 2;
            // x pass
            {
                uint2 BH[3], BL[3];
#pragma unroll
                for (int g = 0; g < 3; g++){
                    size_t idx = bb + (size_t)(16 * g + nbBase) * 64;
                    BH[g] = *(const uint2*)(Bx_hi + idx);
                    BL[g] = *(const uint2*)(Bx_lo + idx);
                }
#pragma unroll
                for (int rb = 0; rb < 2; rb++){
                    uint32_t ah[4], al[4];
                    uint32_t ao = laneOff + (uint32_t)rb * 16 * APITCH + (uint32_t)kt * 32;
                    ldsm4(ah, xH + ao);
                    ldsm4(al, xL + ao);
#pragma unroll
                    for (int g = 0; g < 3; g++){
                        mma_bf16(acc[rb][g], ah, BH[g].x, BH[g].y);
                        mma_bf16(acc[rb][g], al, BH[g].x, BH[g].y);
                        mma_bf16(acc[rb][g], ah, BL[g].x, BL[g].y);
                    }
                }
            }
            // m pass
            if (hasM){
                uint2 BH[3], BL[3];
#pragma unroll
                for (int g = 0; g < 3; g++){
                    size_t idx = bb + (size_t)(16 * g + nbBase) * 64;
                    BH[g] = *(const uint2*)(Bh_hi + idx);
                    BL[g] = *(const uint2*)(Bh_lo + idx);
                }
#pragma unroll
                for (int rb = 0; rb < 2; rb++){
                    uint32_t ah[4], al[4];
                    uint32_t ao = laneOff + (uint32_t)rb * 16 * APITCH + (uint32_t)kt * 32;
                    ldsm4(ah, mH + ao);
                    ldsm4(al, mL + ao);
#pragma unroll
                    for (int g = 0; g < 2; g++){
                        mma_bf16(acc[rb][g], ah, BH[g].x, BH[g].y);
                        mma_bf16(acc[rb][g], al, BH[g].x, BH[g].y);
                        mma_bf16(acc[rb][g], ah, BL[g].x, BL[g].y);
                    }
                    mma_bf16(acc[rb][3], ah, BH[2].x, BH[2].y);
                    mma_bf16(acc[rb][3], al, BH[2].x, BH[2].y);
                    mma_bf16(acc[rb][3], ah, BL[2].x, BL[2].y);
                }
            }
        }

        // epilogue for this col-group
        const int c0 = warp * 16 + j * 8 + (lane & 3) * 2;
        const float br0 = sb[c0],       br1 = sb[c0 + 1];
        const float bz0 = sb[128 + c0], bz1 = sb[128 + c0 + 1];
        const float bn0 = sb[256 + c0], bn1 = sb[256 + c0 + 1];
#pragma unroll
        for (int rb = 0; rb < 2; rb++){
#pragma unroll
            for (int half = 0; half < 2; half++){
                int row = rb * 16 + (lane >> 2) + half * 8;
                int nl = row0 + row;
                if (nl < NPL){
                    float mv0 = 0.f, mv1 = 0.f;
                    if (hasM){
                        uint32_t o = (uint32_t)row * APITCH + (uint32_t)c0 * 2;
                        uint32_t Hm = *(const uint32_t*)(sMH + o);
                        uint32_t Lm = *(const uint32_t*)(sML + o);
                        mv0 = bflo(Hm) + bflo(Lm);
                        mv1 = bfhi(Hm) + bfhi(Lm);
                    }
                    int q0 = half * 2;
                    float r0 = sigmf(acc[rb][0][q0]     + br0);
                    float r1 = sigmf(acc[rb][0][q0 + 1] + br1);
                    float z0 = sigmf(acc[rb][1][q0]     + bz0);
                    float z1 = sigmf(acc[rb][1][q0 + 1] + bz1);
                    float n0 = tanhfast(acc[rb][2][q0]     + bn0 + r0 * acc[rb][3][q0]);
                    float n1 = tanhfast(acc[rb][2][q0 + 1] + bn1 + r1 * acc[rb][3][q0 + 1]);
                    *(float2*)(hdst + (size_t)(s + nl) * HD + c0) =
                        make_float2((1.f - z0) * n0 + z0 * mv0,
                                    (1.f - z1) * n1 + z1 * mv1);
                }
            }
        }
    }
}

// ---------------- out = h[index_map] ----------------
__global__ void k_gather4(const int* __restrict__ imap, float4* __restrict__ out){
    int i = blockIdx.x * blockDim.x + threadIdx.x;
    if (i < NN * 32){
        int node = i >> 5, q = i & 31;
        out[i] = *(const float4*)(g_h + (size_t)__ldg(&imap[node]) * HD + q * 4);
    }
}

extern "C" void kernel_launch(void* const* d_in, const int* in_sizes, int n_in,
                              void* d_out, int out_size){
    const float* feats = (const float*)d_in[0];
    const float* wx    = (const float*)d_in[1];  // (256,1,384)
    const float* wh    = (const float*)d_in[2];  // (2,128,1,384)
    const float* bs    = (const float*)d_in[3];  // (2,1,384)
    const int*   esrc  = (const int*)  d_in[4];
    // d_in[5] edge_dst unused: dsts contiguous by construction (repeat, DEG=8)
    const int*   imap  = (const int*)  d_in[6];
    float*       out   = (float*)d_out;

    void *px, *ph;
    cudaGetSymbolAddress(&px, g_x);
    cudaGetSymbolAddress(&ph, g_h);

    const int EV = NN * 32;  // float4 elements
    k_prep<<<(196608 + 255) / 256, 256>>>(wx, wh);
    k_scatter4<<<(EV + 255) / 256, 256>>>((const float4*)feats, imap);

    for (int layer = 0; layer < 2; layer++){
        const float* xs = (layer == 0) ? (const float*)px : (const float*)ph;
        const float* b  = bs + (size_t)layer * G3;
        for (int lvl = 0; lvl < NLVL; lvl++)
            k_lv<<<LV_NCTA, LV_NT>>>(xs, (float*)ph, esrc, b, layer, lvl);
    }

    k_gather4<<<(EV + 255) / 256, 256>>>(imap, (float4*)out);
}